// round 17
// baseline (speedup 1.0000x reference)
#include <cuda_runtime.h>
#include <cuda_fp16.h>

#define TT 1024
#define HH 128
#define BB 256
#define BPC 2            // batch rows per CTA
#define NTHREADS 256
#define K2_THREADS 256

// 256*1024*128 halves = 64 MB scratch for hidden-state sequence [B,T,H]
__device__ __half g_hseq_h[(size_t)BB * TT * HH];

__device__ __forceinline__ unsigned long long ffma2(unsigned long long a,
                                                    unsigned long long b,
                                                    unsigned long long c) {
    unsigned long long d;
    asm("fma.rn.f32x2 %0, %1, %2, %3;" : "=l"(d) : "l"(a), "l"(b), "l"(c));
    return d;
}

__device__ __forceinline__ unsigned long long addf2(unsigned long long a,
                                                    unsigned long long b) {
    unsigned long long d;
    asm("add.rn.f32x2 %0, %1, %2;" : "=l"(d) : "l"(a), "l"(b));
    return d;
}

__device__ __forceinline__ float2 unpack_f32x2(unsigned long long v) {
    float2 f;
    asm("mov.b64 {%0, %1}, %2;" : "=f"(f.x), "=f"(f.y) : "l"(v));
    return f;
}

// ---------------------------------------------------------------------------
// Kernel 1: serial recurrence. One CTA = 2 batch rows, 128 threads/row,
// rows decoupled via private named barriers.
// NEW decomposition (combine-chain cut): thread (upair, khalf) computes
// partials for units u0=wid*32+2*upair, u1=u0+1 over k-half
// [64*khalf, 64*khalf+64). Cross-lane combine is ONE shfl_xor(1): lane
// khalf=0 finalizes u0, khalf=1 finalizes u1 -> u_final = wid*32+lane
// (identity: conflict-free STS, coalesced STG). FFMA2 count unchanged (64).
// ---------------------------------------------------------------------------
__global__ __launch_bounds__(NTHREADS, 1)
void rnn_rec_kernel(const float* __restrict__ x,      // [B, T, 1]
                    const float* __restrict__ W_ih,   // [H, 1]
                    const float* __restrict__ W_hh,   // [H, H]
                    const float* __restrict__ b_ih,   // [H]
                    const float* __restrict__ b_hh)   // [H]
{
    __shared__ __align__(16) float xs[BPC][TT];        // 8 KB input preload
    __shared__ __align__(16) float hs[2][BPC][HH];     // double-buffered h

    const int tid   = threadIdx.x;
    const int bl    = tid >> 7;         // batch-local row 0/1
    const int r     = tid & 127;        // thread id within row
    const int wid   = r >> 5;           // warp within row (0..3)
    const int lane  = r & 31;
    const int khalf = lane & 1;         // which 64-wide k-half
    const int upair = lane >> 1;        // unit-pair index (0..15)
    const int b     = blockIdx.x * BPC + bl;
    const int bar   = bl + 1;           // named barrier: this row's 4 warps

    const int u0   = wid * 32 + upair * 2;   // my two FFMA units
    const int u1   = u0 + 1;
    const int ufin = wid * 32 + lane;        // unit I finalize (= u0 or u1)
    const int k0   = khalf * 64;             // my k-half start

    // ---- weights: 2 units x 64 k -> 2 x 32 packed f32x2 registers ----
    unsigned long long w0[32], w1[32];
    {
        const ulonglong2* p0 = (const ulonglong2*)(W_hh + u0 * HH + k0);
        const ulonglong2* p1 = (const ulonglong2*)(W_hh + u1 * HH + k0);
        #pragma unroll
        for (int j = 0; j < 16; j++) {
            ulonglong2 v0 = p0[j];
            w0[2 * j]     = v0.x;
            w0[2 * j + 1] = v0.y;
            ulonglong2 v1 = p1[j];
            w1[2 * j]     = v1.x;
            w1[2 * j + 1] = v1.y;
        }
    }
    const float wih  = W_ih[ufin];
    const float bias = b_ih[ufin] + b_hh[ufin];

    // ---- preload x for this row ----
    for (int i = r; i < TT; i += 128)
        xs[bl][i] = x[b * TT + i];

    if (khalf == 0) {
        hs[0][bl][u0] = 0.0f;
        hs[0][bl][u1] = 0.0f;
    }

    asm volatile("bar.sync %0, 128;" :: "r"(bar) : "memory");

    __half* hout = g_hseq_h + (size_t)b * TT * HH + ufin;

    for (int t = 0; t < TT; t++) {
        const int cur = t & 1;
        const int nxt = cur ^ 1;

        const float xb = fmaf(xs[bl][t], wih, bias);   // off critical tail

        // ---- load my 64-float k-half (16 LDS.128; 2 distinct bcast addrs) ----
        unsigned long long hreg[32];
        {
            const ulonglong2* hv = (const ulonglong2*)&hs[cur][bl][k0];
            #pragma unroll
            for (int j = 0; j < 16; j++) {
                ulonglong2 v = hv[j];
                hreg[2 * j]     = v.x;
                hreg[2 * j + 1] = v.y;
            }
        }

        // ---- 4 independent 16-deep packed FMA chains (2 per unit) ----
        unsigned long long a0a = 0ull, a0b = 0ull, a1a = 0ull, a1b = 0ull;
        #pragma unroll
        for (int j = 0; j < 16; j++) {
            a0a = ffma2(hreg[2 * j],     w0[2 * j],     a0a);
            a0b = ffma2(hreg[2 * j + 1], w0[2 * j + 1], a0b);
            a1a = ffma2(hreg[2 * j],     w1[2 * j],     a1a);
            a1b = ffma2(hreg[2 * j + 1], w1[2 * j + 1], a1b);
        }
        unsigned long long a0 = addf2(a0a, a0b);
        unsigned long long a1 = addf2(a1a, a1b);
        float2 f0 = unpack_f32x2(a0);
        float2 f1 = unpack_f32x2(a1);
        float s0 = f0.x + f0.y;        // partial(u0, my k-half)
        float s1 = f1.x + f1.y;        // partial(u1, my k-half)

        // ---- single-shfl combine: partner holds the other k-half.
        // I finalize u_{khalf}; partner needs my partial of the unit THEY
        // finalize: send s1 if khalf==0 (partner finalizes u1), else s0.
        float send = khalf ? s0 : s1;
        float recv = __shfl_xor_sync(0xffffffffu, send, 1);
        float own  = (khalf ? s1 : s0) + xb;   // overlaps shfl flight
        float pre  = own + recv;

        // tanh(x) = 1 - 2/(exp(2x)+1)   (EX2 + RCP, ~1e-6 rel err)
        float e  = __expf(pre + pre);
        float hn = 1.0f - __fdividef(2.0f, e + 1.0f);

        hs[nxt][bl][ufin] = hn;                  // conflict-free STS.32
        hout[(size_t)t * HH] = __float2half(hn); // coalesced export

        asm volatile("bar.sync %0, 128;" :: "r"(bar) : "memory");
    }
}

// ---------------------------------------------------------------------------
// Kernel 2: streaming logits from fp16 hidden states (64 MB total).
// out[b,t,c] = sum_h h[b,t,h]*W_fc[c,h] + b_fc[c];  fp32 accumulation.
// ---------------------------------------------------------------------------
__global__ __launch_bounds__(K2_THREADS)
void rnn_fc_kernel(const float* __restrict__ W_fc,   // [2, H]
                   const float* __restrict__ b_fc,   // [2]
                   float* __restrict__ out)          // [B, T, 2]
{
    __shared__ __align__(16) float wf[2][HH];
    __shared__ float bf[2];

    const int tid = threadIdx.x;
    if (tid < HH) {
        wf[0][tid] = W_fc[tid];
        wf[1][tid] = W_fc[HH + tid];
    }
    if (tid < 2) bf[tid] = b_fc[tid];
    __syncthreads();

    const size_t r = (size_t)blockIdx.x * K2_THREADS + tid;   // row in [0, B*T)
    const uint4* hv = (const uint4*)(g_hseq_h + r * HH);      // 16 x 16B

    float acc0 = 0.0f, acc1 = 0.0f;
    #pragma unroll
    for (int j = 0; j < HH / 8; j++) {          // 16 LDG.128
        uint4 v = __ldcs(&hv[j]);
        const __half2* hp = (const __half2*)&v;
        #pragma unroll
        for (int k = 0; k < 4; k++) {
            float2 hf = __half22float2(hp[k]);
            int idx = j * 8 + k * 2;
            acc0 = fmaf(hf.x, wf[0][idx],     acc0);
            acc0 = fmaf(hf.y, wf[0][idx + 1], acc0);
            acc1 = fmaf(hf.x, wf[1][idx],     acc1);
            acc1 = fmaf(hf.y, wf[1][idx + 1], acc1);
        }
    }
    float2 res = make_float2(acc0 + bf[0], acc1 + bf[1]);
    ((float2*)out)[r] = res;           // coalesced 8B/thread
}

extern "C" void kernel_launch(void* const* d_in, const int* in_sizes, int n_in,
                              void* d_out, int out_size) {
    const float* x    = (const float*)d_in[0];
    const float* W_ih = (const float*)d_in[1];
    const float* W_hh = (const float*)d_in[2];
    const float* b_ih = (const float*)d_in[3];
    const float* b_hh = (const float*)d_in[4];
    const float* W_fc = (const float*)d_in[5];
    const float* b_fc = (const float*)d_in[6];
    float* out = (float*)d_out;

    rnn_rec_kernel<<<BB / BPC, NTHREADS>>>(x, W_ih, W_hh, b_ih, b_hh);
    rnn_fc_kernel<<<(BB * TT) / K2_THREADS, K2_THREADS>>>(W_fc, b_fc, out);
}